// round 1
// baseline (speedup 1.0000x reference)
#include <cuda_runtime.h>
#include <math.h>

#define S  4096
#define D  2048
#define FF 8192
#define EPSF 1.1920929e-07f

// ---------------- scratch (device globals; no allocation allowed) ----------
__device__ float g_h[(size_t)S * D];
__device__ float g_q[(size_t)S * D];
__device__ float g_k[(size_t)S * D];
__device__ float g_v[(size_t)S * D];
__device__ float g_scores[(size_t)S * S];
__device__ float g_attnv[(size_t)S * D];
__device__ float g_x1[(size_t)S * D];
__device__ float g_gate[(size_t)S * FF];
__device__ float g_up[(size_t)S * FF];

// ---------------------------------------------------------------------------
// GEMM: C[M,N] = alpha * A[M,K] @ op(B) (+ residual)
//   BT=true : B is [N,K] row-major (NT gemm, i.e. x @ W^T)
//   BT=false: B is [K,N] row-major (NN gemm, i.e. scores @ v)
// Tile 128x128x16, 256 threads, 8x8 per thread. M,N,K multiples of 128/16.
// ---------------------------------------------------------------------------
template <bool BT>
__global__ __launch_bounds__(256)
void gemm_kernel(const float* __restrict__ A, const float* __restrict__ B,
                 float* __restrict__ C, const float* __restrict__ residual,
                 int M, int N, int K, float alpha)
{
    __shared__ float As[16][128];
    __shared__ float Bs[16][128];

    const int tid = threadIdx.x;
    const int bm  = blockIdx.y * 128;
    const int bn  = blockIdx.x * 128;
    const int tx  = tid & 15;   // column group
    const int ty  = tid >> 4;   // row group

    float acc[8][8];
#pragma unroll
    for (int i = 0; i < 8; i++)
#pragma unroll
        for (int j = 0; j < 8; j++) acc[i][j] = 0.f;

    for (int k0 = 0; k0 < K; k0 += 16) {
#pragma unroll
        for (int r = 0; r < 2; r++) {
            int idx = tid + 256 * r;
            {
                int row = idx >> 2;
                int col = (idx & 3) << 2;
                float4 a = *(const float4*)(A + (size_t)(bm + row) * K + k0 + col);
                As[col + 0][row] = a.x;
                As[col + 1][row] = a.y;
                As[col + 2][row] = a.z;
                As[col + 3][row] = a.w;
            }
            if (BT) {
                int row = idx >> 2;
                int col = (idx & 3) << 2;
                float4 b = *(const float4*)(B + (size_t)(bn + row) * K + k0 + col);
                Bs[col + 0][row] = b.x;
                Bs[col + 1][row] = b.y;
                Bs[col + 2][row] = b.z;
                Bs[col + 3][row] = b.w;
            } else {
                int row = idx >> 5;           // 0..15
                int col = (idx & 31) << 2;    // 0..124
                float4 b = *(const float4*)(B + (size_t)(k0 + row) * N + bn + col);
                *(float4*)&Bs[row][col] = b;
            }
        }
        __syncthreads();

#pragma unroll
        for (int kk = 0; kk < 16; kk++) {
            float av[8], bv[8];
            *(float4*)(av)     = *(const float4*)&As[kk][ty * 8];
            *(float4*)(av + 4) = *(const float4*)&As[kk][ty * 8 + 4];
            *(float4*)(bv)     = *(const float4*)&Bs[kk][tx * 8];
            *(float4*)(bv + 4) = *(const float4*)&Bs[kk][tx * 8 + 4];
#pragma unroll
            for (int i = 0; i < 8; i++)
#pragma unroll
                for (int j = 0; j < 8; j++)
                    acc[i][j] += av[i] * bv[j];
        }
        __syncthreads();
    }

#pragma unroll
    for (int i = 0; i < 8; i++) {
        int row = bm + ty * 8 + i;
#pragma unroll
        for (int jj = 0; jj < 2; jj++) {
            int col = bn + tx * 8 + jj * 4;
            float4 v;
            v.x = acc[i][jj * 4 + 0] * alpha;
            v.y = acc[i][jj * 4 + 1] * alpha;
            v.z = acc[i][jj * 4 + 2] * alpha;
            v.w = acc[i][jj * 4 + 3] * alpha;
            if (residual) {
                float4 rsd = *(const float4*)(residual + (size_t)row * N + col);
                v.x += rsd.x; v.y += rsd.y; v.z += rsd.z; v.w += rsd.w;
            }
            *(float4*)(C + (size_t)row * N + col) = v;
        }
    }
}

// ---------------------------------------------------------------------------
// RMSNorm: out[r,:] = x[r,:] * rsqrt(mean(x^2)+eps) * w   (block per row)
// ---------------------------------------------------------------------------
__global__ __launch_bounds__(256)
void rmsnorm_kernel(const float* __restrict__ x, const float* __restrict__ w,
                    float* __restrict__ out)
{
    const int row = blockIdx.x;
    const int tid = threadIdx.x;
    const float* xr = x + (size_t)row * D;
    float vals[8];
    float local = 0.f;
#pragma unroll
    for (int i = 0; i < 8; i++) {
        float v = xr[tid + i * 256];
        vals[i] = v;
        local += v * v;
    }
    // warp reduce
#pragma unroll
    for (int o = 16; o > 0; o >>= 1)
        local += __shfl_xor_sync(0xffffffffu, local, o);
    __shared__ float sh[8];
    if ((tid & 31) == 0) sh[tid >> 5] = local;
    __syncthreads();
    if (tid == 0) {
        float s = 0.f;
#pragma unroll
        for (int i = 0; i < 8; i++) s += sh[i];
        sh[0] = rsqrtf(s / (float)D + EPSF);
    }
    __syncthreads();
    float scale = sh[0];
    float* orow = out + (size_t)row * D;
#pragma unroll
    for (int i = 0; i < 8; i++)
        orow[tid + i * 256] = vals[i] * scale * w[tid + i * 256];
}

// ---------------------------------------------------------------------------
// RoPE (in place): [x1,x2] -> [x1*c - x2*s, x1*s + x2*c], halves split at D/2
// ---------------------------------------------------------------------------
__global__ __launch_bounds__(256)
void rope_kernel(float* __restrict__ q, const float* __restrict__ cosb,
                 const float* __restrict__ sinb)
{
    const int row = blockIdx.x;
    const int tid = threadIdx.x;
    float* qr = q + (size_t)row * D;
    const float* cr = cosb + (size_t)row * (D / 2);
    const float* sr = sinb + (size_t)row * (D / 2);
#pragma unroll
    for (int i = 0; i < 4; i++) {
        int j = tid + i * 256;           // 0 .. D/2-1
        float c = cr[j], s = sr[j];
        float x1 = qr[j], x2 = qr[j + D / 2];
        qr[j]         = x1 * c - x2 * s;
        qr[j + D / 2] = x1 * s + x2 * c;
    }
}

// ---------------------------------------------------------------------------
// Row softmax over S=4096 (block per row, values stay in registers)
// ---------------------------------------------------------------------------
__global__ __launch_bounds__(256)
void softmax_kernel(float* __restrict__ scores)
{
    const int row = blockIdx.x;
    const int tid = threadIdx.x;
    float* p = scores + (size_t)row * S;
    float vals[16];
    float m = -1e30f;
#pragma unroll
    for (int i = 0; i < 16; i++) {
        float v = p[tid + i * 256];
        vals[i] = v;
        m = fmaxf(m, v);
    }
#pragma unroll
    for (int o = 16; o > 0; o >>= 1)
        m = fmaxf(m, __shfl_xor_sync(0xffffffffu, m, o));
    __shared__ float sh[8];
    if ((tid & 31) == 0) sh[tid >> 5] = m;
    __syncthreads();
    if (tid == 0) {
        float mm = sh[0];
#pragma unroll
        for (int i = 1; i < 8; i++) mm = fmaxf(mm, sh[i]);
        sh[0] = mm;
    }
    __syncthreads();
    m = sh[0];
    __syncthreads();   // protect sh reuse below
    float sum = 0.f;
#pragma unroll
    for (int i = 0; i < 16; i++) {
        vals[i] = expf(vals[i] - m);
        sum += vals[i];
    }
#pragma unroll
    for (int o = 16; o > 0; o >>= 1)
        sum += __shfl_xor_sync(0xffffffffu, sum, o);
    if ((tid & 31) == 0) sh[tid >> 5] = sum;
    __syncthreads();
    if (tid == 0) {
        float ss = 0.f;
#pragma unroll
        for (int i = 0; i < 8; i++) ss += sh[i];
        sh[0] = 1.f / ss;
    }
    __syncthreads();
    float inv = sh[0];
#pragma unroll
    for (int i = 0; i < 16; i++)
        p[tid + i * 256] = vals[i] * inv;
}

// ---------------------------------------------------------------------------
// SwiGLU: gate = silu(gate) * up  (vectorized, in place on gate)
// ---------------------------------------------------------------------------
__global__ __launch_bounds__(256)
void swiglu_kernel(float* __restrict__ gate, const float* __restrict__ up)
{
    int i = blockIdx.x * 256 + threadIdx.x;   // over float4s, exact fit
    float4 g = ((const float4*)gate)[i];
    float4 u = ((const float4*)up)[i];
    g.x = g.x / (1.f + expf(-g.x)) * u.x;
    g.y = g.y / (1.f + expf(-g.y)) * u.y;
    g.z = g.z / (1.f + expf(-g.z)) * u.z;
    g.w = g.w / (1.f + expf(-g.w)) * u.w;
    ((float4*)gate)[i] = g;
}

// ---------------------------------------------------------------------------
// launch
// ---------------------------------------------------------------------------
extern "C" void kernel_launch(void* const* d_in, const int* in_sizes, int n_in,
                              void* d_out, int out_size)
{
    const float* x      = (const float*)d_in[0];
    const float* w_rn1  = (const float*)d_in[1];
    const float* wq     = (const float*)d_in[2];
    const float* wk     = (const float*)d_in[3];
    const float* wv     = (const float*)d_in[4];
    const float* wo     = (const float*)d_in[5];
    const float* w_rn2  = (const float*)d_in[6];
    const float* w_gate = (const float*)d_in[7];
    const float* w_up   = (const float*)d_in[8];
    const float* w_down = (const float*)d_in[9];
    const float* cosb   = (const float*)d_in[10];
    const float* sinb   = (const float*)d_in[11];
    float* out = (float*)d_out;

    float *h, *q, *k, *v, *scores, *attnv, *x1, *gate, *up;
    cudaGetSymbolAddress((void**)&h,      g_h);
    cudaGetSymbolAddress((void**)&q,      g_q);
    cudaGetSymbolAddress((void**)&k,      g_k);
    cudaGetSymbolAddress((void**)&v,      g_v);
    cudaGetSymbolAddress((void**)&scores, g_scores);
    cudaGetSymbolAddress((void**)&attnv,  g_attnv);
    cudaGetSymbolAddress((void**)&x1,     g_x1);
    cudaGetSymbolAddress((void**)&gate,   g_gate);
    cudaGetSymbolAddress((void**)&up,     g_up);

    const float inv_scale = 1.f / sqrtf((float)D);

    dim3 gDD(D / 128, S / 128);    // [S,D] outputs
    dim3 gSS(S / 128, S / 128);    // [S,S] scores
    dim3 gFF(FF / 128, S / 128);   // [S,FF] outputs

    // h = rmsnorm(x) * w_rn1
    rmsnorm_kernel<<<S, 256>>>(x, w_rn1, h);
    // q,k,v projections (x @ W^T => NT)
    gemm_kernel<true><<<gDD, 256>>>(h, wq, q, nullptr, S, D, D, 1.f);
    gemm_kernel<true><<<gDD, 256>>>(h, wk, k, nullptr, S, D, D, 1.f);
    gemm_kernel<true><<<gDD, 256>>>(h, wv, v, nullptr, S, D, D, 1.f);
    // rope on q, k
    rope_kernel<<<S, 256>>>(q, cosb, sinb);
    rope_kernel<<<S, 256>>>(k, cosb, sinb);
    // scores = q @ k^T / sqrt(D)   (NT, K=D)
    gemm_kernel<true><<<gSS, 256>>>(q, k, scores, nullptr, S, S, D, inv_scale);
    // softmax rows
    softmax_kernel<<<S, 256>>>(scores);
    // attnv = scores @ v           (NN, K=S)
    gemm_kernel<false><<<gDD, 256>>>(scores, v, attnv, nullptr, S, D, S, 1.f);
    // x1 = x + attnv @ wo^T        (NT + fused residual)
    gemm_kernel<true><<<gDD, 256>>>(attnv, wo, x1, x, S, D, D, 1.f);
    // h = rmsnorm(x1) * w_rn2
    rmsnorm_kernel<<<S, 256>>>(x1, w_rn2, h);
    // gate/up projections
    gemm_kernel<true><<<gFF, 256>>>(h, w_gate, gate, nullptr, S, FF, D, 1.f);
    gemm_kernel<true><<<gFF, 256>>>(h, w_up,   up,   nullptr, S, FF, D, 1.f);
    // gate = silu(gate) * up
    swiglu_kernel<<<(S * (FF / 4)) / 256, 256>>>(gate, up);
    // out = x1 + gate @ w_down^T   (NT + fused residual, K=FF)
    gemm_kernel<true><<<gDD, 256>>>(gate, w_down, out, x1, S, D, FF, 1.f);
}

// round 4
// speedup vs baseline: 2.4622x; 2.4622x over previous
#include <cuda_runtime.h>
#include <cuda_bf16.h>
#include <stdint.h>
#include <math.h>

#define S  4096
#define D  2048
#define FF 8192
#define EPSF 1.1920929e-07f

#define KC 32                    // bf16 k per chunk
#define OPBYTES (128 * 80)       // one operand tile: 128 rows x 80B (64B data + pad)
#define STGB (4 * OPBYTES)       // Ah, Al, Bh, Bl
#define NSTAGE 4
#define SMEMB (NSTAGE * STGB)    // 163840

// ------------------------- device scratch (no allocs allowed) ---------------
__device__ __nv_bfloat16 g_wq_h[(size_t)D*D],  g_wq_l[(size_t)D*D];
__device__ __nv_bfloat16 g_wk_h[(size_t)D*D],  g_wk_l[(size_t)D*D];
__device__ __nv_bfloat16 g_wv_h[(size_t)D*D],  g_wv_l[(size_t)D*D];
__device__ __nv_bfloat16 g_wo_h[(size_t)D*D],  g_wo_l[(size_t)D*D];
__device__ __nv_bfloat16 g_wg_h[(size_t)FF*D], g_wg_l[(size_t)FF*D];
__device__ __nv_bfloat16 g_wu_h[(size_t)FF*D], g_wu_l[(size_t)FF*D];
__device__ __nv_bfloat16 g_wd_h[(size_t)D*FF], g_wd_l[(size_t)D*FF];
__device__ __nv_bfloat16 g_h_h[(size_t)S*D],   g_h_l[(size_t)S*D];
__device__ __nv_bfloat16 g_q_h[(size_t)S*D],   g_q_l[(size_t)S*D];
__device__ __nv_bfloat16 g_k_h[(size_t)S*D],   g_k_l[(size_t)S*D];
__device__ __nv_bfloat16 g_vt_h[(size_t)D*S],  g_vt_l[(size_t)D*S];
__device__ __nv_bfloat16 g_p_h[(size_t)S*S],   g_p_l[(size_t)S*S];
__device__ __nv_bfloat16 g_av_h[(size_t)S*D],  g_av_l[(size_t)S*D];
__device__ __nv_bfloat16 g_h2_h[(size_t)S*D],  g_h2_l[(size_t)S*D];
__device__ __nv_bfloat16 g_act_h[(size_t)S*FF],g_act_l[(size_t)S*FF];
__device__ float g_qf[(size_t)S*D];
__device__ float g_kf[(size_t)S*D];
__device__ float g_vf[(size_t)S*D];
__device__ float g_sc[(size_t)S*S];
__device__ float g_avf[(size_t)S*D];
__device__ float g_x1[(size_t)S*D];
__device__ float g_gf[(size_t)S*FF];
__device__ float g_uf[(size_t)S*FF];

// ------------------------- helpers ------------------------------------------
__device__ __forceinline__ uint32_t smem_u32(const void* p) {
    uint32_t a;
    asm("{ .reg .u64 t; cvta.to.shared.u64 t, %1; cvt.u32.u64 %0, t; }"
        : "=r"(a) : "l"(p));
    return a;
}

__device__ __forceinline__ void cpasync16(uint32_t dst, const void* src) {
    asm volatile("cp.async.cg.shared.global [%0], [%1], 16;"
                 :: "r"(dst), "l"(src) : "memory");
}

__device__ __forceinline__ void ldsm4(uint32_t addr, uint32_t& r0, uint32_t& r1,
                                      uint32_t& r2, uint32_t& r3) {
    asm volatile("ldmatrix.sync.aligned.m8n8.x4.shared.b16 {%0,%1,%2,%3}, [%4];"
                 : "=r"(r0), "=r"(r1), "=r"(r2), "=r"(r3) : "r"(addr));
}

__device__ __forceinline__ void mma16816(float* c, const uint32_t* a, const uint32_t* b) {
    asm volatile("mma.sync.aligned.m16n8k16.row.col.f32.bf16.bf16.f32 "
                 "{%0,%1,%2,%3}, {%4,%5,%6,%7}, {%8,%9}, {%0,%1,%2,%3};"
                 : "+f"(c[0]), "+f"(c[1]), "+f"(c[2]), "+f"(c[3])
                 : "r"(a[0]), "r"(a[1]), "r"(a[2]), "r"(a[3]),
                   "r"(b[0]), "r"(b[1]));
}

// ------------------------- tensor-core split GEMM ----------------------------
// C[M,N] = alpha * (Ahi+Alo)[M,K] @ (Bhi+Blo)[N,K]^T (+res). bf16 3-pass split.
__global__ __launch_bounds__(256, 1)
void gemm_mma(const __nv_bfloat16* __restrict__ Ah, const __nv_bfloat16* __restrict__ Al,
              const __nv_bfloat16* __restrict__ Bh, const __nv_bfloat16* __restrict__ Bl,
              float* __restrict__ C, const float* __restrict__ res,
              int M, int N, int K, float alpha)
{
    extern __shared__ __align__(128) char smem[];
    const int tid = threadIdx.x;
    const int wid = tid >> 5, lane = tid & 31;
    const int warp_m = wid & 3, warp_n = wid >> 2;
    const int bm = blockIdx.y * 128, bn = blockIdx.x * 128;
    const uint32_t sb = smem_u32(smem);
    const int nch = K / KC;

    float acc[2][8][4];
#pragma unroll
    for (int mt = 0; mt < 2; mt++)
#pragma unroll
        for (int nt = 0; nt < 8; nt++)
#pragma unroll
            for (int e = 0; e < 4; e++) acc[mt][nt][e] = 0.f;

    const int lrow = tid >> 2;   // 0..63
    const int lc   = tid & 3;    // 16B chunk within 64B row

    // ---- stage loader -------------------------------------------------------
    auto issue = [&](int stage, int chunk) {
        const int k0 = chunk * KC;
#pragma unroll
        for (int r = 0; r < 2; r++) {
            const int row = lrow + r * 64;
            const uint32_t d = sb + stage * STGB + row * 80 + lc * 16;
            const size_t ga = (size_t)(bm + row) * K + k0 + lc * 8;
            const size_t gb = (size_t)(bn + row) * K + k0 + lc * 8;
            cpasync16(d,               Ah + ga);
            cpasync16(d + OPBYTES,     Al + ga);
            cpasync16(d + 2 * OPBYTES, Bh + gb);
            cpasync16(d + 3 * OPBYTES, Bl + gb);
        }
    };

    // prologue
#pragma unroll
    for (int s = 0; s < NSTAGE - 1; s++) {
        issue(s, s);
        asm volatile("cp.async.commit_group;" ::: "memory");
    }

    // ldmatrix lane addressing
    const int quad = lane >> 3, l8 = lane & 7;
    const int a_r = (quad & 1) * 8 + l8;   // row within 16-row m-tile
    const int a_c = (quad >> 1) * 8;       // k offset within 16
    const int b_r = (quad >> 1) * 8 + l8;  // n-row within 16-row pair
    const int b_c = (quad & 1) * 8;        // k offset within 16

    for (int i = 0; i < nch; i++) {
        asm volatile("cp.async.wait_group 2;" ::: "memory");
        __syncthreads();
        if (i + NSTAGE - 1 < nch) issue((i + NSTAGE - 1) & (NSTAGE - 1), i + NSTAGE - 1);
        asm volatile("cp.async.commit_group;" ::: "memory");

        const uint32_t st = sb + (i & (NSTAGE - 1)) * STGB;
#pragma unroll
        for (int ks = 0; ks < 2; ks++) {
            const int ko = ks * 16;
            uint32_t ah[2][4], al[2][4], b[8][2];
#pragma unroll
            for (int mt = 0; mt < 2; mt++) {
                const uint32_t ad = st + (warp_m * 32 + mt * 16 + a_r) * 80 + (a_c + ko) * 2;
                ldsm4(ad,            ah[mt][0], ah[mt][1], ah[mt][2], ah[mt][3]);
                ldsm4(ad + OPBYTES,  al[mt][0], al[mt][1], al[mt][2], al[mt][3]);
            }
#pragma unroll
            for (int p = 0; p < 4; p++) {
                const uint32_t bd = st + 2 * OPBYTES +
                                    (warp_n * 64 + p * 16 + b_r) * 80 + (b_c + ko) * 2;
                ldsm4(bd, b[2 * p][0], b[2 * p][1], b[2 * p + 1][0], b[2 * p + 1][1]);
            }
            // pass 1: hi*hi
#pragma unroll
            for (int mt = 0; mt < 2; mt++)
#pragma unroll
                for (int nt = 0; nt < 8; nt++) mma16816(acc[mt][nt], ah[mt], b[nt]);
            // pass 2: lo*hi
#pragma unroll
            for (int mt = 0; mt < 2; mt++)
#pragma unroll
                for (int nt = 0; nt < 8; nt++) mma16816(acc[mt][nt], al[mt], b[nt]);
            // pass 3: hi*lo (reuse b regs for Blo)
#pragma unroll
            for (int p = 0; p < 4; p++) {
                const uint32_t bd = st + 3 * OPBYTES +
                                    (warp_n * 64 + p * 16 + b_r) * 80 + (b_c + ko) * 2;
                ldsm4(bd, b[2 * p][0], b[2 * p][1], b[2 * p + 1][0], b[2 * p + 1][1]);
            }
#pragma unroll
            for (int mt = 0; mt < 2; mt++)
#pragma unroll
                for (int nt = 0; nt < 8; nt++) mma16816(acc[mt][nt], ah[mt], b[nt]);
        }
    }

    // epilogue
    const int g2 = lane >> 2, t2 = lane & 3;
#pragma unroll
    for (int mt = 0; mt < 2; mt++) {
        const int row0 = bm + warp_m * 32 + mt * 16 + g2;
#pragma unroll
        for (int nt = 0; nt < 8; nt++) {
            const int col = bn + warp_n * 64 + nt * 8 + 2 * t2;
            float2 v0 = make_float2(acc[mt][nt][0] * alpha, acc[mt][nt][1] * alpha);
            float2 v1 = make_float2(acc[mt][nt][2] * alpha, acc[mt][nt][3] * alpha);
            if (res) {
                float2 r0 = *(const float2*)(res + (size_t)row0 * N + col);
                float2 r1 = *(const float2*)(res + (size_t)(row0 + 8) * N + col);
                v0.x += r0.x; v0.y += r0.y; v1.x += r1.x; v1.y += r1.y;
            }
            *(float2*)(C + (size_t)row0 * N + col) = v0;
            *(float2*)(C + (size_t)(row0 + 8) * N + col) = v1;
        }
    }
}

// ------------------------- elementwise kernels ------------------------------
__device__ __forceinline__ void split1(float x, __nv_bfloat16* hp, __nv_bfloat16* lp) {
    __nv_bfloat16 h = __float2bfloat16(x);
    *hp = h;
    *lp = __float2bfloat16(x - __bfloat162float(h));
}

__global__ __launch_bounds__(256)
void k_split(const float* __restrict__ src, __nv_bfloat16* __restrict__ h,
             __nv_bfloat16* __restrict__ l, size_t n4)
{
    size_t i = (size_t)blockIdx.x * 256 + threadIdx.x;
    if (i >= n4) return;
    float4 v = ((const float4*)src)[i];
    __nv_bfloat16 hv[4], lv[4];
    split1(v.x, &hv[0], &lv[0]);
    split1(v.y, &hv[1], &lv[1]);
    split1(v.z, &hv[2], &lv[2]);
    split1(v.w, &hv[3], &lv[3]);
    *(uint2*)(h + 4 * i) = *(uint2*)hv;
    *(uint2*)(l + 4 * i) = *(uint2*)lv;
}

__global__ __launch_bounds__(256)
void k_rmsnorm_split(const float* __restrict__ x, const float* __restrict__ w,
                     __nv_bfloat16* __restrict__ oh, __nv_bfloat16* __restrict__ ol)
{
    const int row = blockIdx.x, tid = threadIdx.x;
    const float* xr = x + (size_t)row * D;
    float vals[8], local = 0.f;
#pragma unroll
    for (int i = 0; i < 8; i++) {
        float v = xr[tid + i * 256];
        vals[i] = v;
        local += v * v;
    }
#pragma unroll
    for (int o = 16; o > 0; o >>= 1)
        local += __shfl_xor_sync(0xffffffffu, local, o);
    __shared__ float sh[8];
    if ((tid & 31) == 0) sh[tid >> 5] = local;
    __syncthreads();
    if (tid == 0) {
        float s = 0.f;
#pragma unroll
        for (int i = 0; i < 8; i++) s += sh[i];
        sh[0] = rsqrtf(s / (float)D + EPSF);
    }
    __syncthreads();
    float scale = sh[0];
#pragma unroll
    for (int i = 0; i < 8; i++) {
        int j = tid + i * 256;
        split1(vals[i] * scale * w[j], &oh[(size_t)row * D + j], &ol[(size_t)row * D + j]);
    }
}

__global__ __launch_bounds__(256)
void k_rope_split(const float* __restrict__ qf, const float* __restrict__ cosb,
                  const float* __restrict__ sinb,
                  __nv_bfloat16* __restrict__ oh, __nv_bfloat16* __restrict__ ol)
{
    const int row = blockIdx.x, tid = threadIdx.x;
    const float* qr = qf + (size_t)row * D;
    const float* cr = cosb + (size_t)row * (D / 2);
    const float* sr = sinb + (size_t)row * (D / 2);
#pragma unroll
    for (int i = 0; i < 4; i++) {
        int j = tid + i * 256;
        float c = cr[j], s = sr[j];
        float x1 = qr[j], x2 = qr[j + D / 2];
        size_t o1 = (size_t)row * D + j, o2 = o1 + D / 2;
        split1(x1 * c - x2 * s, &oh[o1], &ol[o1]);
        split1(x1 * s + x2 * c, &oh[o2], &ol[o2]);
    }
}

__global__ __launch_bounds__(256)
void k_softmax_split(const float* __restrict__ scores,
                     __nv_bfloat16* __restrict__ ph, __nv_bfloat16* __restrict__ pl)
{
    const int row = blockIdx.x, tid = threadIdx.x;
    const float* p = scores + (size_t)row * S;
    float vals[16], m = -1e30f;
#pragma unroll
    for (int i = 0; i < 16; i++) {
        float v = p[tid + i * 256];
        vals[i] = v;
        m = fmaxf(m, v);
    }
#pragma unroll
    for (int o = 16; o > 0; o >>= 1)
        m = fmaxf(m, __shfl_xor_sync(0xffffffffu, m, o));
    __shared__ float sh[8];
    if ((tid & 31) == 0) sh[tid >> 5] = m;
    __syncthreads();
    if (tid == 0) {
        float mm = sh[0];
#pragma unroll
        for (int i = 1; i < 8; i++) mm = fmaxf(mm, sh[i]);
        sh[0] = mm;
    }
    __syncthreads();
    m = sh[0];
    __syncthreads();
    float sum = 0.f;
#pragma unroll
    for (int i = 0; i < 16; i++) {
        vals[i] = expf(vals[i] - m);
        sum += vals[i];
    }
#pragma unroll
    for (int o = 16; o > 0; o >>= 1)
        sum += __shfl_xor_sync(0xffffffffu, sum, o);
    if ((tid & 31) == 0) sh[tid >> 5] = sum;
    __syncthreads();
    if (tid == 0) {
        float ss = 0.f;
#pragma unroll
        for (int i = 0; i < 8; i++) ss += sh[i];
        sh[0] = 1.f / ss;
    }
    __syncthreads();
    float inv = sh[0];
#pragma unroll
    for (int i = 0; i < 16; i++) {
        size_t o = (size_t)row * S + tid + i * 256;
        split1(vals[i] * inv, &ph[o], &pl[o]);
    }
}

__global__ __launch_bounds__(256)
void k_transpose_split(const float* __restrict__ v,
                       __nv_bfloat16* __restrict__ th, __nv_bfloat16* __restrict__ tl)
{
    __shared__ float t[32][33];
    const int d0 = blockIdx.x * 32, s0 = blockIdx.y * 32;
    const int tx = threadIdx.x & 31, ty = threadIdx.x >> 5;
#pragma unroll
    for (int j = ty; j < 32; j += 8)
        t[j][tx] = v[(size_t)(s0 + j) * D + d0 + tx];
    __syncthreads();
#pragma unroll
    for (int j = ty; j < 32; j += 8) {
        float val = t[tx][j];
        size_t o = (size_t)(d0 + j) * S + s0 + tx;
        split1(val, &th[o], &tl[o]);
    }
}

__global__ __launch_bounds__(256)
void k_swiglu_split(const float* __restrict__ g, const float* __restrict__ u,
                    __nv_bfloat16* __restrict__ oh, __nv_bfloat16* __restrict__ ol)
{
    size_t i = (size_t)blockIdx.x * 256 + threadIdx.x;
    float4 gv = ((const float4*)g)[i];
    float4 uv = ((const float4*)u)[i];
    float r0 = gv.x / (1.f + expf(-gv.x)) * uv.x;
    float r1 = gv.y / (1.f + expf(-gv.y)) * uv.y;
    float r2 = gv.z / (1.f + expf(-gv.z)) * uv.z;
    float r3 = gv.w / (1.f + expf(-gv.w)) * uv.w;
    __nv_bfloat16 hv[4], lv[4];
    split1(r0, &hv[0], &lv[0]);
    split1(r1, &hv[1], &lv[1]);
    split1(r2, &hv[2], &lv[2]);
    split1(r3, &hv[3], &lv[3]);
    *(uint2*)(oh + 4 * i) = *(uint2*)hv;
    *(uint2*)(ol + 4 * i) = *(uint2*)lv;
}

// ------------------------- launch -------------------------------------------
static inline void split_launch(const float* src, __nv_bfloat16* h, __nv_bfloat16* l, size_t n) {
    size_t n4 = n / 4;
    k_split<<<(unsigned)((n4 + 255) / 256), 256>>>(src, h, l, n4);
}

extern "C" void kernel_launch(void* const* d_in, const int* in_sizes, int n_in,
                              void* d_out, int out_size)
{
    const float* x      = (const float*)d_in[0];
    const float* w_rn1  = (const float*)d_in[1];
    const float* wq     = (const float*)d_in[2];
    const float* wk     = (const float*)d_in[3];
    const float* wv     = (const float*)d_in[4];
    const float* wo     = (const float*)d_in[5];
    const float* w_rn2  = (const float*)d_in[6];
    const float* w_gate = (const float*)d_in[7];
    const float* w_up   = (const float*)d_in[8];
    const float* w_down = (const float*)d_in[9];
    const float* cosb   = (const float*)d_in[10];
    const float* sinb   = (const float*)d_in[11];
    float* out = (float*)d_out;

    static int smem_set = 0;
    if (!smem_set) {
        cudaFuncSetAttribute(gemm_mma, cudaFuncAttributeMaxDynamicSharedMemorySize, SMEMB);
        smem_set = 1;
    }

#define SYM(p, s) do { void* _t; cudaGetSymbolAddress(&_t, s); p = (decltype(p))_t; } while (0)
    __nv_bfloat16 *wq_h, *wq_l, *wk_h, *wk_l, *wv_h, *wv_l, *wo_h, *wo_l;
    __nv_bfloat16 *wg_h, *wg_l, *wu_h, *wu_l, *wd_h, *wd_l;
    __nv_bfloat16 *h_h, *h_l, *q_h, *q_l, *k_h, *k_l, *vt_h, *vt_l;
    __nv_bfloat16 *p_h, *p_l, *av_h, *av_l, *h2_h, *h2_l, *act_h, *act_l;
    float *qf, *kf, *vf, *sc, *avf, *x1, *gf, *uf;
    SYM(wq_h, g_wq_h); SYM(wq_l, g_wq_l); SYM(wk_h, g_wk_h); SYM(wk_l, g_wk_l);
    SYM(wv_h, g_wv_h); SYM(wv_l, g_wv_l); SYM(wo_h, g_wo_h); SYM(wo_l, g_wo_l);
    SYM(wg_h, g_wg_h); SYM(wg_l, g_wg_l); SYM(wu_h, g_wu_h); SYM(wu_l, g_wu_l);
    SYM(wd_h, g_wd_h); SYM(wd_l, g_wd_l);
    SYM(h_h, g_h_h);   SYM(h_l, g_h_l);   SYM(q_h, g_q_h);   SYM(q_l, g_q_l);
    SYM(k_h, g_k_h);   SYM(k_l, g_k_l);   SYM(vt_h, g_vt_h); SYM(vt_l, g_vt_l);
    SYM(p_h, g_p_h);   SYM(p_l, g_p_l);   SYM(av_h, g_av_h); SYM(av_l, g_av_l);
    SYM(h2_h, g_h2_h); SYM(h2_l, g_h2_l); SYM(act_h, g_act_h); SYM(act_l, g_act_l);
    SYM(qf, g_qf); SYM(kf, g_kf); SYM(vf, g_vf); SYM(sc, g_sc);
    SYM(avf, g_avf); SYM(x1, g_x1); SYM(gf, g_gf); SYM(uf, g_uf);
#undef SYM

    const float inv_scale = 1.f / sqrtf((float)D);

    // weight splits
    split_launch(wq, wq_h, wq_l, (size_t)D * D);
    split_launch(wk, wk_h, wk_l, (size_t)D * D);
    split_launch(wv, wv_h, wv_l, (size_t)D * D);
    split_launch(wo, wo_h, wo_l, (size_t)D * D);
    split_launch(w_gate, wg_h, wg_l, (size_t)FF * D);
    split_launch(w_up,   wu_h, wu_l, (size_t)FF * D);
    split_launch(w_down, wd_h, wd_l, (size_t)D * FF);

    // h = rmsnorm(x)*w_rn1, split
    k_rmsnorm_split<<<S, 256>>>(x, w_rn1, h_h, h_l);

    dim3 gDD(D / 128, S / 128);
    dim3 gSS(S / 128, S / 128);
    dim3 gFFd(FF / 128, S / 128);

    // q,k,v projections
    gemm_mma<<<gDD, 256, SMEMB>>>(h_h, h_l, wq_h, wq_l, qf, nullptr, S, D, D, 1.f);
    gemm_mma<<<gDD, 256, SMEMB>>>(h_h, h_l, wk_h, wk_l, kf, nullptr, S, D, D, 1.f);
    gemm_mma<<<gDD, 256, SMEMB>>>(h_h, h_l, wv_h, wv_l, vf, nullptr, S, D, D, 1.f);
    // rope + split
    k_rope_split<<<S, 256>>>(qf, cosb, sinb, q_h, q_l);
    k_rope_split<<<S, 256>>>(kf, cosb, sinb, k_h, k_l);
    // v transpose + split
    k_transpose_split<<<dim3(D / 32, S / 32), 256>>>(vf, vt_h, vt_l);
    // scores = q @ k^T / sqrt(D)
    gemm_mma<<<gSS, 256, SMEMB>>>(q_h, q_l, k_h, k_l, sc, nullptr, S, S, D, inv_scale);
    // softmax + split
    k_softmax_split<<<S, 256>>>(sc, p_h, p_l);
    // attnv = P @ V  (B = V^T [D,S])
    gemm_mma<<<gDD, 256, SMEMB>>>(p_h, p_l, vt_h, vt_l, avf, nullptr, S, D, S, 1.f);
    // split attnv
    split_launch(avf, av_h, av_l, (size_t)S * D);
    // x1 = x + attnv @ wo^T
    gemm_mma<<<gDD, 256, SMEMB>>>(av_h, av_l, wo_h, wo_l, x1, x, S, D, D, 1.f);
    // h2 = rmsnorm(x1)*w_rn2
    k_rmsnorm_split<<<S, 256>>>(x1, w_rn2, h2_h, h2_l);
    // gate / up
    gemm_mma<<<gFFd, 256, SMEMB>>>(h2_h, h2_l, wg_h, wg_l, gf, nullptr, S, FF, D, 1.f);
    gemm_mma<<<gFFd, 256, SMEMB>>>(h2_h, h2_l, wu_h, wu_l, uf, nullptr, S, FF, D, 1.f);
    // swiglu + split
    k_swiglu_split<<<(S * (FF / 4)) / 256, 256>>>(gf, uf, act_h, act_l);
    // out = x1 + act @ w_down^T
    gemm_mma<<<gDD, 256, SMEMB>>>(act_h, act_l, wd_h, wd_l, out, x1, S, D, FF, 1.f);
}

// round 5
// speedup vs baseline: 2.7557x; 1.1192x over previous
#include <cuda_runtime.h>
#include <cuda_bf16.h>
#include <stdint.h>
#include <math.h>

#define S  4096
#define D  2048
#define FF 8192
#define EPSF 1.1920929e-07f

#define KC 32                    // bf16 k per chunk
#define OPBYTES (128 * 80)       // one operand tile: 128 rows x 80B (64B data + pad)
#define STGB (4 * OPBYTES)       // Ah, Al, Bh, Bl
#define NSTAGE 2
#define SMEMB (NSTAGE * STGB)    // 81920 -> 2 CTAs/SM

// ------------------------- device scratch (no allocs allowed) ---------------
__device__ __nv_bfloat16 g_wq_h[(size_t)D*D],  g_wq_l[(size_t)D*D];
__device__ __nv_bfloat16 g_wk_h[(size_t)D*D],  g_wk_l[(size_t)D*D];
__device__ __nv_bfloat16 g_wv_h[(size_t)D*D],  g_wv_l[(size_t)D*D];
__device__ __nv_bfloat16 g_wo_h[(size_t)D*D],  g_wo_l[(size_t)D*D];
__device__ __nv_bfloat16 g_wg_h[(size_t)FF*D], g_wg_l[(size_t)FF*D];
__device__ __nv_bfloat16 g_wu_h[(size_t)FF*D], g_wu_l[(size_t)FF*D];
__device__ __nv_bfloat16 g_wd_h[(size_t)D*FF], g_wd_l[(size_t)D*FF];
__device__ __nv_bfloat16 g_h_h[(size_t)S*D],   g_h_l[(size_t)S*D];
__device__ __nv_bfloat16 g_q_h[(size_t)S*D],   g_q_l[(size_t)S*D];
__device__ __nv_bfloat16 g_k_h[(size_t)S*D],   g_k_l[(size_t)S*D];
__device__ __nv_bfloat16 g_vt_h[(size_t)D*S],  g_vt_l[(size_t)D*S];
__device__ __nv_bfloat16 g_p_h[(size_t)S*S],   g_p_l[(size_t)S*S];
__device__ __nv_bfloat16 g_av_h[(size_t)S*D],  g_av_l[(size_t)S*D];
__device__ __nv_bfloat16 g_h2_h[(size_t)S*D],  g_h2_l[(size_t)S*D];
__device__ __nv_bfloat16 g_act_h[(size_t)S*FF],g_act_l[(size_t)S*FF];
__device__ float g_qf[(size_t)S*D];
__device__ float g_kf[(size_t)S*D];
__device__ float g_vf[(size_t)S*D];
__device__ float g_sc[(size_t)S*S];
__device__ float g_avf[(size_t)S*D];
__device__ float g_x1[(size_t)S*D];
__device__ float g_gf[(size_t)S*FF];
__device__ float g_uf[(size_t)S*FF];

// ------------------------- helpers ------------------------------------------
__device__ __forceinline__ uint32_t smem_u32(const void* p) {
    uint32_t a;
    asm("{ .reg .u64 t; cvta.to.shared.u64 t, %1; cvt.u32.u64 %0, t; }"
        : "=r"(a) : "l"(p));
    return a;
}

__device__ __forceinline__ void cpasync16(uint32_t dst, const void* src) {
    asm volatile("cp.async.cg.shared.global [%0], [%1], 16;"
                 :: "r"(dst), "l"(src) : "memory");
}

__device__ __forceinline__ void ldsm4(uint32_t addr, uint32_t& r0, uint32_t& r1,
                                      uint32_t& r2, uint32_t& r3) {
    asm volatile("ldmatrix.sync.aligned.m8n8.x4.shared.b16 {%0,%1,%2,%3}, [%4];"
                 : "=r"(r0), "=r"(r1), "=r"(r2), "=r"(r3) : "r"(addr));
}

__device__ __forceinline__ void mma16816(float* c, const uint32_t* a, const uint32_t* b) {
    asm volatile("mma.sync.aligned.m16n8k16.row.col.f32.bf16.bf16.f32 "
                 "{%0,%1,%2,%3}, {%4,%5,%6,%7}, {%8,%9}, {%0,%1,%2,%3};"
                 : "+f"(c[0]), "+f"(c[1]), "+f"(c[2]), "+f"(c[3])
                 : "r"(a[0]), "r"(a[1]), "r"(a[2]), "r"(a[3]),
                   "r"(b[0]), "r"(b[1]));
}

// ------------------------- tensor-core split GEMM ----------------------------
// C[M,N] = alpha * (Ahi+Alo)[M,K] @ (Bhi+Blo)[N,K]^T (+res). bf16 3-pass split.
// 2-stage cp.async double buffer, 2 CTAs/SM.
__global__ __launch_bounds__(256, 2)
void gemm_mma(const __nv_bfloat16* __restrict__ Ah, const __nv_bfloat16* __restrict__ Al,
              const __nv_bfloat16* __restrict__ Bh, const __nv_bfloat16* __restrict__ Bl,
              float* __restrict__ C, const float* __restrict__ res,
              int M, int N, int K, float alpha)
{
    extern __shared__ __align__(128) char smem[];
    const int tid = threadIdx.x;
    const int wid = tid >> 5, lane = tid & 31;
    const int warp_m = wid & 3, warp_n = wid >> 2;
    const int bm = blockIdx.y * 128, bn = blockIdx.x * 128;
    const uint32_t sb = smem_u32(smem);
    const int nch = K / KC;

    float acc[2][8][4];
#pragma unroll
    for (int mt = 0; mt < 2; mt++)
#pragma unroll
        for (int nt = 0; nt < 8; nt++)
#pragma unroll
            for (int e = 0; e < 4; e++) acc[mt][nt][e] = 0.f;

    const int lrow = tid >> 2;   // 0..63
    const int lc   = tid & 3;    // 16B chunk within 64B row

    // ---- stage loader -------------------------------------------------------
    auto issue = [&](int stage, int chunk) {
        const int k0 = chunk * KC;
#pragma unroll
        for (int r = 0; r < 2; r++) {
            const int row = lrow + r * 64;
            const uint32_t d = sb + stage * STGB + row * 80 + lc * 16;
            const size_t ga = (size_t)(bm + row) * K + k0 + lc * 8;
            const size_t gb = (size_t)(bn + row) * K + k0 + lc * 8;
            cpasync16(d,               Ah + ga);
            cpasync16(d + OPBYTES,     Al + ga);
            cpasync16(d + 2 * OPBYTES, Bh + gb);
            cpasync16(d + 3 * OPBYTES, Bl + gb);
        }
    };

    // prologue: stage 0 in flight
    issue(0, 0);
    asm volatile("cp.async.commit_group;" ::: "memory");

    // ldmatrix lane addressing
    const int quad = lane >> 3, l8 = lane & 7;
    const int a_r = (quad & 1) * 8 + l8;   // row within 16-row m-tile
    const int a_c = (quad >> 1) * 8;       // k offset within 16
    const int b_r = (quad >> 1) * 8 + l8;  // n-row within 16-row pair
    const int b_c = (quad & 1) * 8;        // k offset within 16

    for (int i = 0; i < nch; i++) {
        asm volatile("cp.async.wait_group 0;" ::: "memory");
        __syncthreads();
        if (i + 1 < nch) issue((i + 1) & (NSTAGE - 1), i + 1);
        asm volatile("cp.async.commit_group;" ::: "memory");

        const uint32_t st = sb + (i & (NSTAGE - 1)) * STGB;
#pragma unroll
        for (int ks = 0; ks < 2; ks++) {
            const int ko = ks * 16;
            uint32_t ah[2][4], al[2][4], b[8][2];
#pragma unroll
            for (int mt = 0; mt < 2; mt++) {
                const uint32_t ad = st + (warp_m * 32 + mt * 16 + a_r) * 80 + (a_c + ko) * 2;
                ldsm4(ad,            ah[mt][0], ah[mt][1], ah[mt][2], ah[mt][3]);
                ldsm4(ad + OPBYTES,  al[mt][0], al[mt][1], al[mt][2], al[mt][3]);
            }
#pragma unroll
            for (int p = 0; p < 4; p++) {
                const uint32_t bd = st + 2 * OPBYTES +
                                    (warp_n * 64 + p * 16 + b_r) * 80 + (b_c + ko) * 2;
                ldsm4(bd, b[2 * p][0], b[2 * p][1], b[2 * p + 1][0], b[2 * p + 1][1]);
            }
            // pass 1: hi*hi
#pragma unroll
            for (int mt = 0; mt < 2; mt++)
#pragma unroll
                for (int nt = 0; nt < 8; nt++) mma16816(acc[mt][nt], ah[mt], b[nt]);
            // pass 2: lo*hi
#pragma unroll
            for (int mt = 0; mt < 2; mt++)
#pragma unroll
                for (int nt = 0; nt < 8; nt++) mma16816(acc[mt][nt], al[mt], b[nt]);
            // pass 3: hi*lo (reuse b regs for Blo)
#pragma unroll
            for (int p = 0; p < 4; p++) {
                const uint32_t bd = st + 3 * OPBYTES +
                                    (warp_n * 64 + p * 16 + b_r) * 80 + (b_c + ko) * 2;
                ldsm4(bd, b[2 * p][0], b[2 * p][1], b[2 * p + 1][0], b[2 * p + 1][1]);
            }
#pragma unroll
            for (int mt = 0; mt < 2; mt++)
#pragma unroll
                for (int nt = 0; nt < 8; nt++) mma16816(acc[mt][nt], ah[mt], b[nt]);
        }
    }

    // epilogue
    const int g2 = lane >> 2, t2 = lane & 3;
#pragma unroll
    for (int mt = 0; mt < 2; mt++) {
        const int row0 = bm + warp_m * 32 + mt * 16 + g2;
#pragma unroll
        for (int nt = 0; nt < 8; nt++) {
            const int col = bn + warp_n * 64 + nt * 8 + 2 * t2;
            float2 v0 = make_float2(acc[mt][nt][0] * alpha, acc[mt][nt][1] * alpha);
            float2 v1 = make_float2(acc[mt][nt][2] * alpha, acc[mt][nt][3] * alpha);
            if (res) {
                float2 r0 = *(const float2*)(res + (size_t)row0 * N + col);
                float2 r1 = *(const float2*)(res + (size_t)(row0 + 8) * N + col);
                v0.x += r0.x; v0.y += r0.y; v1.x += r1.x; v1.y += r1.y;
            }
            *(float2*)(C + (size_t)row0 * N + col) = v0;
            *(float2*)(C + (size_t)(row0 + 8) * N + col) = v1;
        }
    }
}

// ------------------------- elementwise kernels ------------------------------
__device__ __forceinline__ void split1(float x, __nv_bfloat16* hp, __nv_bfloat16* lp) {
    __nv_bfloat16 h = __float2bfloat16(x);
    *hp = h;
    *lp = __float2bfloat16(x - __bfloat162float(h));
}

__global__ __launch_bounds__(256)
void k_split(const float* __restrict__ src, __nv_bfloat16* __restrict__ h,
             __nv_bfloat16* __restrict__ l, size_t n4)
{
    size_t i = (size_t)blockIdx.x * 256 + threadIdx.x;
    if (i >= n4) return;
    float4 v = ((const float4*)src)[i];
    __nv_bfloat16 hv[4], lv[4];
    split1(v.x, &hv[0], &lv[0]);
    split1(v.y, &hv[1], &lv[1]);
    split1(v.z, &hv[2], &lv[2]);
    split1(v.w, &hv[3], &lv[3]);
    *(uint2*)(h + 4 * i) = *(uint2*)hv;
    *(uint2*)(l + 4 * i) = *(uint2*)lv;
}

__global__ __launch_bounds__(256)
void k_rmsnorm_split(const float* __restrict__ x, const float* __restrict__ w,
                     __nv_bfloat16* __restrict__ oh, __nv_bfloat16* __restrict__ ol)
{
    const int row = blockIdx.x, tid = threadIdx.x;
    const float* xr = x + (size_t)row * D;
    float vals[8], local = 0.f;
#pragma unroll
    for (int i = 0; i < 8; i++) {
        float v = xr[tid + i * 256];
        vals[i] = v;
        local += v * v;
    }
#pragma unroll
    for (int o = 16; o > 0; o >>= 1)
        local += __shfl_xor_sync(0xffffffffu, local, o);
    __shared__ float sh[8];
    if ((tid & 31) == 0) sh[tid >> 5] = local;
    __syncthreads();
    if (tid == 0) {
        float s = 0.f;
#pragma unroll
        for (int i = 0; i < 8; i++) s += sh[i];
        sh[0] = rsqrtf(s / (float)D + EPSF);
    }
    __syncthreads();
    float scale = sh[0];
#pragma unroll
    for (int i = 0; i < 8; i++) {
        int j = tid + i * 256;
        split1(vals[i] * scale * w[j], &oh[(size_t)row * D + j], &ol[(size_t)row * D + j]);
    }
}

__global__ __launch_bounds__(256)
void k_rope_split(const float* __restrict__ qf, const float* __restrict__ cosb,
                  const float* __restrict__ sinb,
                  __nv_bfloat16* __restrict__ oh, __nv_bfloat16* __restrict__ ol)
{
    const int row = blockIdx.x, tid = threadIdx.x;
    const float* qr = qf + (size_t)row * D;
    const float* cr = cosb + (size_t)row * (D / 2);
    const float* sr = sinb + (size_t)row * (D / 2);
#pragma unroll
    for (int i = 0; i < 4; i++) {
        int j = tid + i * 256;
        float c = cr[j], s = sr[j];
        float x1 = qr[j], x2 = qr[j + D / 2];
        size_t o1 = (size_t)row * D + j, o2 = o1 + D / 2;
        split1(x1 * c - x2 * s, &oh[o1], &ol[o1]);
        split1(x1 * s + x2 * c, &oh[o2], &ol[o2]);
    }
}

__global__ __launch_bounds__(256)
void k_softmax_split(const float* __restrict__ scores,
                     __nv_bfloat16* __restrict__ ph, __nv_bfloat16* __restrict__ pl)
{
    const int row = blockIdx.x, tid = threadIdx.x;
    const float* p = scores + (size_t)row * S;
    float vals[16], m = -1e30f;
#pragma unroll
    for (int i = 0; i < 16; i++) {
        float v = p[tid + i * 256];
        vals[i] = v;
        m = fmaxf(m, v);
    }
#pragma unroll
    for (int o = 16; o > 0; o >>= 1)
        m = fmaxf(m, __shfl_xor_sync(0xffffffffu, m, o));
    __shared__ float sh[8];
    if ((tid & 31) == 0) sh[tid >> 5] = m;
    __syncthreads();
    if (tid == 0) {
        float mm = sh[0];
#pragma unroll
        for (int i = 1; i < 8; i++) mm = fmaxf(mm, sh[i]);
        sh[0] = mm;
    }
    __syncthreads();
    m = sh[0];
    __syncthreads();
    float sum = 0.f;
#pragma unroll
    for (int i = 0; i < 16; i++) {
        vals[i] = expf(vals[i] - m);
        sum += vals[i];
    }
#pragma unroll
    for (int o = 16; o > 0; o >>= 1)
        sum += __shfl_xor_sync(0xffffffffu, sum, o);
    if ((tid & 31) == 0) sh[tid >> 5] = sum;
    __syncthreads();
    if (tid == 0) {
        float ss = 0.f;
#pragma unroll
        for (int i = 0; i < 8; i++) ss += sh[i];
        sh[0] = 1.f / ss;
    }
    __syncthreads();
    float inv = sh[0];
#pragma unroll
    for (int i = 0; i < 16; i++) {
        size_t o = (size_t)row * S + tid + i * 256;
        split1(vals[i] * inv, &ph[o], &pl[o]);
    }
}

__global__ __launch_bounds__(256)
void k_transpose_split(const float* __restrict__ v,
                       __nv_bfloat16* __restrict__ th, __nv_bfloat16* __restrict__ tl)
{
    __shared__ float t[32][33];
    const int d0 = blockIdx.x * 32, s0 = blockIdx.y * 32;
    const int tx = threadIdx.x & 31, ty = threadIdx.x >> 5;
#pragma unroll
    for (int j = ty; j < 32; j += 8)
        t[j][tx] = v[(size_t)(s0 + j) * D + d0 + tx];
    __syncthreads();
#pragma unroll
    for (int j = ty; j < 32; j += 8) {
        float val = t[tx][j];
        size_t o = (size_t)(d0 + j) * S + s0 + tx;
        split1(val, &th[o], &tl[o]);
    }
}

__global__ __launch_bounds__(256)
void k_swiglu_split(const float* __restrict__ g, const float* __restrict__ u,
                    __nv_bfloat16* __restrict__ oh, __nv_bfloat16* __restrict__ ol)
{
    size_t i = (size_t)blockIdx.x * 256 + threadIdx.x;
    float4 gv = ((const float4*)g)[i];
    float4 uv = ((const float4*)u)[i];
    float r0 = gv.x / (1.f + expf(-gv.x)) * uv.x;
    float r1 = gv.y / (1.f + expf(-gv.y)) * uv.y;
    float r2 = gv.z / (1.f + expf(-gv.z)) * uv.z;
    float r3 = gv.w / (1.f + expf(-gv.w)) * uv.w;
    __nv_bfloat16 hv[4], lv[4];
    split1(r0, &hv[0], &lv[0]);
    split1(r1, &hv[1], &lv[1]);
    split1(r2, &hv[2], &lv[2]);
    split1(r3, &hv[3], &lv[3]);
    *(uint2*)(oh + 4 * i) = *(uint2*)hv;
    *(uint2*)(ol + 4 * i) = *(uint2*)lv;
}

// ------------------------- launch -------------------------------------------
static inline void split_launch(const float* src, __nv_bfloat16* h, __nv_bfloat16* l, size_t n) {
    size_t n4 = n / 4;
    k_split<<<(unsigned)((n4 + 255) / 256), 256>>>(src, h, l, n4);
}

extern "C" void kernel_launch(void* const* d_in, const int* in_sizes, int n_in,
                              void* d_out, int out_size)
{
    const float* x      = (const float*)d_in[0];
    const float* w_rn1  = (const float*)d_in[1];
    const float* wq     = (const float*)d_in[2];
    const float* wk     = (const float*)d_in[3];
    const float* wv     = (const float*)d_in[4];
    const float* wo     = (const float*)d_in[5];
    const float* w_rn2  = (const float*)d_in[6];
    const float* w_gate = (const float*)d_in[7];
    const float* w_up   = (const float*)d_in[8];
    const float* w_down = (const float*)d_in[9];
    const float* cosb   = (const float*)d_in[10];
    const float* sinb   = (const float*)d_in[11];
    float* out = (float*)d_out;

    static int smem_set = 0;
    if (!smem_set) {
        cudaFuncSetAttribute(gemm_mma, cudaFuncAttributeMaxDynamicSharedMemorySize, SMEMB);
        smem_set = 1;
    }

#define SYM(p, s) do { void* _t; cudaGetSymbolAddress(&_t, s); p = (decltype(p))_t; } while (0)
    __nv_bfloat16 *wq_h, *wq_l, *wk_h, *wk_l, *wv_h, *wv_l, *wo_h, *wo_l;
    __nv_bfloat16 *wg_h, *wg_l, *wu_h, *wu_l, *wd_h, *wd_l;
    __nv_bfloat16 *h_h, *h_l, *q_h, *q_l, *k_h, *k_l, *vt_h, *vt_l;
    __nv_bfloat16 *p_h, *p_l, *av_h, *av_l, *h2_h, *h2_l, *act_h, *act_l;
    float *qf, *kf, *vf, *sc, *avf, *x1, *gf, *uf;
    SYM(wq_h, g_wq_h); SYM(wq_l, g_wq_l); SYM(wk_h, g_wk_h); SYM(wk_l, g_wk_l);
    SYM(wv_h, g_wv_h); SYM(wv_l, g_wv_l); SYM(wo_h, g_wo_h); SYM(wo_l, g_wo_l);
    SYM(wg_h, g_wg_h); SYM(wg_l, g_wg_l); SYM(wu_h, g_wu_h); SYM(wu_l, g_wu_l);
    SYM(wd_h, g_wd_h); SYM(wd_l, g_wd_l);
    SYM(h_h, g_h_h);   SYM(h_l, g_h_l);   SYM(q_h, g_q_h);   SYM(q_l, g_q_l);
    SYM(k_h, g_k_h);   SYM(k_l, g_k_l);   SYM(vt_h, g_vt_h); SYM(vt_l, g_vt_l);
    SYM(p_h, g_p_h);   SYM(p_l, g_p_l);   SYM(av_h, g_av_h); SYM(av_l, g_av_l);
    SYM(h2_h, g_h2_h); SYM(h2_l, g_h2_l); SYM(act_h, g_act_h); SYM(act_l, g_act_l);
    SYM(qf, g_qf); SYM(kf, g_kf); SYM(vf, g_vf); SYM(sc, g_sc);
    SYM(avf, g_avf); SYM(x1, g_x1); SYM(gf, g_gf); SYM(uf, g_uf);
#undef SYM

    const float inv_scale = 1.f / sqrtf((float)D);

    // weight splits
    split_launch(wq, wq_h, wq_l, (size_t)D * D);
    split_launch(wk, wk_h, wk_l, (size_t)D * D);
    split_launch(wv, wv_h, wv_l, (size_t)D * D);
    split_launch(wo, wo_h, wo_l, (size_t)D * D);
    split_launch(w_gate, wg_h, wg_l, (size_t)FF * D);
    split_launch(w_up,   wu_h, wu_l, (size_t)FF * D);
    split_launch(w_down, wd_h, wd_l, (size_t)D * FF);

    // h = rmsnorm(x)*w_rn1, split
    k_rmsnorm_split<<<S, 256>>>(x, w_rn1, h_h, h_l);

    dim3 gDD(D / 128, S / 128);
    dim3 gSS(S / 128, S / 128);
    dim3 gFFd(FF / 128, S / 128);

    // q,k,v projections
    gemm_mma<<<gDD, 256, SMEMB>>>(h_h, h_l, wq_h, wq_l, qf, nullptr, S, D, D, 1.f);
    gemm_mma<<<gDD, 256, SMEMB>>>(h_h, h_l, wk_h, wk_l, kf, nullptr, S, D, D, 1.f);
    gemm_mma<<<gDD, 256, SMEMB>>>(h_h, h_l, wv_h, wv_l, vf, nullptr, S, D, D, 1.f);
    // rope + split
    k_rope_split<<<S, 256>>>(qf, cosb, sinb, q_h, q_l);
    k_rope_split<<<S, 256>>>(kf, cosb, sinb, k_h, k_l);
    // v transpose + split
    k_transpose_split<<<dim3(D / 32, S / 32), 256>>>(vf, vt_h, vt_l);
    // scores = q @ k^T / sqrt(D)
    gemm_mma<<<gSS, 256, SMEMB>>>(q_h, q_l, k_h, k_l, sc, nullptr, S, S, D, inv_scale);
    // softmax + split
    k_softmax_split<<<S, 256>>>(sc, p_h, p_l);
    // attnv = P @ V  (B = V^T [D,S])
    gemm_mma<<<gDD, 256, SMEMB>>>(p_h, p_l, vt_h, vt_l, avf, nullptr, S, D, S, 1.f);
    // split attnv
    split_launch(avf, av_h, av_l, (size_t)S * D);
    // x1 = x + attnv @ wo^T
    gemm_mma<<<gDD, 256, SMEMB>>>(av_h, av_l, wo_h, wo_l, x1, x, S, D, D, 1.f);
    // h2 = rmsnorm(x1)*w_rn2
    k_rmsnorm_split<<<S, 256>>>(x1, w_rn2, h2_h, h2_l);
    // gate / up
    gemm_mma<<<gFFd, 256, SMEMB>>>(h2_h, h2_l, wg_h, wg_l, gf, nullptr, S, FF, D, 1.f);
    gemm_mma<<<gFFd, 256, SMEMB>>>(h2_h, h2_l, wu_h, wu_l, uf, nullptr, S, FF, D, 1.f);
    // swiglu + split
    k_swiglu_split<<<(S * (FF / 4)) / 256, 256>>>(gf, uf, act_h, act_l);
    // out = x1 + act @ w_down^T
    gemm_mma<<<gDD, 256, SMEMB>>>(act_h, act_l, wd_h, wd_l, out, x1, S, D, FF, 1.f);
}